// round 12
// baseline (speedup 1.0000x reference)
#include <cuda_runtime.h>
#include <cuda_bf16.h>
#include <math.h>
#include <stdint.h>

// Problem constants
#define B_   8
#define T_   1024
#define C_   256
#define H_   16
#define D_   16
#define M_   (B_ * T_)        // 8192
#define FF_  (4 * C_)         // 1024
#define EPS_ 1e-5f
#define QSCALE_ 0.360673760222f   // 0.25 * log2(e)

// ---------------- scratch ----------------
__device__ __nv_bfloat16 g_h1b [M_ * C_];
__device__ __nv_bfloat16 g_attb[M_ * C_];
__device__ __nv_bfloat16 g_h2b [M_ * C_];
__device__ __nv_bfloat16 g_h3b [M_ * FF_];
__device__ __nv_bfloat16 g_qkvb[M_ * 3 * C_];   // [row, 768]: q|k|v (bf16)
__device__ float         g_x2  [M_ * C_];
__device__ __nv_bfloat16 g_wqkvt[3 * C_ * C_];  // [768, 256]
__device__ __nv_bfloat16 g_wpt  [C_ * C_];
__device__ __nv_bfloat16 g_w1t  [FF_ * C_];
__device__ __nv_bfloat16 g_w2t  [C_ * FF_];

__device__ __forceinline__ uint32_t smem_u32(const void* p) {
    uint32_t a;
    asm("{ .reg .u64 t; cvta.to.shared.u64 t, %1; cvt.u32.u64 %0, t; }" : "=r"(a) : "l"(p));
    return a;
}
__device__ __forceinline__ float ex2f(float x) {
    float y;
    asm("ex2.approx.ftz.f32 %0, %1;" : "=f"(y) : "f"(x));
    return y;
}
#define CP_ASYNC16(dst, src) \
    asm volatile("cp.async.cg.shared.global [%0], [%1], 16;" :: "r"(dst), "l"(src))
#define CP_COMMIT() asm volatile("cp.async.commit_group;" ::: "memory")
#define CP_WAIT(n)  asm volatile("cp.async.wait_group %0;" :: "n"(n) : "memory")

// ---------------- LN body (device) ----------------
__device__ __forceinline__ void ln_row(const float* __restrict__ x, const float* __restrict__ g,
                                       const float* __restrict__ b, __nv_bfloat16* __restrict__ y,
                                       int row, int lane)
{
    const float* xr = x + (size_t)row * C_;
    float v[8], s = 0.f;
#pragma unroll
    for (int i = 0; i < 8; i++) { v[i] = xr[lane + 32 * i]; s += v[i]; }
#pragma unroll
    for (int o = 16; o > 0; o >>= 1) s += __shfl_xor_sync(0xffffffffu, s, o);
    float mu = s * (1.f / C_);
    float var = 0.f;
#pragma unroll
    for (int i = 0; i < 8; i++) { float d = v[i] - mu; var += d * d; }
#pragma unroll
    for (int o = 16; o > 0; o >>= 1) var += __shfl_xor_sync(0xffffffffu, var, o);
    float rstd = rsqrtf(var * (1.f / C_) + EPS_);
    __nv_bfloat16* yr = y + (size_t)row * C_;
#pragma unroll
    for (int i = 0; i < 8; i++) {
        int c = lane + 32 * i;
        yr[c] = __float2bfloat16((v[i] - mu) * rstd * g[c] + b[c]);
    }
}

// ---------------- prep: weight transposes + ln1, one launch ----------------
__global__ void prep_kernel(const float* __restrict__ Wq, const float* __restrict__ Wk,
                            const float* __restrict__ Wv, const float* __restrict__ Wp,
                            const float* __restrict__ W1, const float* __restrict__ W2,
                            __nv_bfloat16* __restrict__ wqkvt, __nv_bfloat16* __restrict__ wpt,
                            __nv_bfloat16* __restrict__ w1t, __nv_bfloat16* __restrict__ w2t,
                            const float* __restrict__ x, const float* __restrict__ g1,
                            const float* __restrict__ be1, __nv_bfloat16* __restrict__ h1b)
{
    int bid = blockIdx.x;
    if (bid >= 768) {
        int row = (bid - 768) * 8 + (threadIdx.x >> 5);
        ln_row(x, g1, be1, h1b, row, threadIdx.x & 31);
        return;
    }
    __shared__ float t[32][33];
    const float* in; __nv_bfloat16* out; int K, N, tt;
    if (bid < 192)       { int w = bid >> 6; tt = bid & 63;
                           in = (w == 0) ? Wq : (w == 1) ? Wk : Wv;
                           out = wqkvt + w * C_ * C_; K = C_; N = C_; }
    else if (bid < 256)  { tt = bid - 192; in = Wp; out = wpt; K = C_;  N = C_;  }
    else if (bid < 512)  { tt = bid - 256; in = W1; out = w1t; K = C_;  N = FF_; }
    else                 { tt = bid - 512; in = W2; out = w2t; K = FF_; N = C_;  }
    int ntx = N >> 5;
    int n0 = (tt % ntx) * 32, k0 = (tt / ntx) * 32;
    int tx = threadIdx.x & 31, ty = threadIdx.x >> 5;
#pragma unroll
    for (int i = ty; i < 32; i += 8)
        t[i][tx] = in[(size_t)(k0 + i) * N + n0 + tx];
    __syncthreads();
#pragma unroll
    for (int i = ty; i < 32; i += 8)
        out[(size_t)(n0 + i) * K + k0 + tx] = __float2bfloat16(t[tx][i]);
}

// ---------------- bf16 mma.sync GEMM, 4-stage pipeline (lookahead 2) ----------------
// 64x128 block tile, BK=32, 256 threads (2x4 warps, 32x32 per warp).
#define GF_BIAS 1
#define GF_RELU 2
#define GF_RES  4
#define BM 64
#define BN 128
#define BK 32
#define PITCH 40
#define STG 4
#define STAGE_BYTES 15360            // (BM + BN) * PITCH * 2
#define A_BYTES 5120                 // BM * PITCH * 2
#define GEMM_DSM (STG * STAGE_BYTES) // 61440

__global__ __launch_bounds__(256) void mma_gemm(
    const __nv_bfloat16* __restrict__ A, const __nv_bfloat16* __restrict__ Bt,
    const float* __restrict__ bias, const float* __restrict__ res,
    float* __restrict__ outf, __nv_bfloat16* __restrict__ outb,
    int N, int K, int flags)
{
    extern __shared__ __align__(16) char dsm[];

    const int tid  = threadIdx.x;
    const int wid  = tid >> 5;
    const int lane = tid & 31;
    const int warp_m = wid >> 2;
    const int warp_n = wid & 3;
    const int row0 = blockIdx.y * BM;
    const int col0 = blockIdx.x * BN;

    const uint32_t sbase = smem_u32(dsm);

    const int l_row = tid >> 2;
    const int l_c8  = (tid & 3) << 3;

    float acc[2][4][4];
#pragma unroll
    for (int i = 0; i < 2; i++)
#pragma unroll
        for (int j = 0; j < 4; j++)
#pragma unroll
            for (int r = 0; r < 4; r++) acc[i][j][r] = 0.f;

    const int nch = K / BK;

    // prologue: issue chunks 0..2
#pragma unroll
    for (int p = 0; p < 3; p++) {
        int k0 = p * BK;
        uint32_t baseA = sbase + (uint32_t)(p * STAGE_BYTES);
        uint32_t baseB = baseA + A_BYTES;
        CP_ASYNC16(baseA + (uint32_t)(l_row * PITCH + l_c8) * 2,
                   A + (size_t)(row0 + l_row) * K + k0 + l_c8);
#pragma unroll
        for (int v = 0; v < 2; v++) {
            int brow = l_row + v * 64;
            CP_ASYNC16(baseB + (uint32_t)(brow * PITCH + l_c8) * 2,
                       Bt + (size_t)(col0 + brow) * K + k0 + l_c8);
        }
        CP_COMMIT();
    }

    for (int ch = 0; ch < nch; ch++) {
        int rem = nch - 1 - ch;
        if (rem >= 2)      { CP_WAIT(2); }
        else if (rem == 1) { CP_WAIT(1); }
        else               { CP_WAIT(0); }
        __syncthreads();   // stage (ch+3)%STG last read at iter ch-1 -> safe to refill

        if (ch + 3 < nch) {
            int k0 = (ch + 3) * BK;
            int nb = (ch + 3) % STG;
            uint32_t baseA = sbase + (uint32_t)(nb * STAGE_BYTES);
            uint32_t baseB = baseA + A_BYTES;
            CP_ASYNC16(baseA + (uint32_t)(l_row * PITCH + l_c8) * 2,
                       A + (size_t)(row0 + l_row) * K + k0 + l_c8);
#pragma unroll
            for (int v = 0; v < 2; v++) {
                int brow = l_row + v * 64;
                CP_ASYNC16(baseB + (uint32_t)(brow * PITCH + l_c8) * 2,
                           Bt + (size_t)(col0 + brow) * K + k0 + l_c8);
            }
            CP_COMMIT();
        }

        int buf = ch % STG;
        uint32_t aBase = sbase + (uint32_t)(buf * STAGE_BYTES);
        uint32_t bBase = aBase + A_BYTES;

#pragma unroll
        for (int kk = 0; kk < 2; kk++) {
            uint32_t a[2][4], b[4][2];
#pragma unroll
            for (int i = 0; i < 2; i++) {
                int r = warp_m * 32 + i * 16 + (lane & 15);
                int c = kk * 16 + ((lane >> 4) << 3);
                uint32_t addr = aBase + (uint32_t)(r * PITCH + c) * 2;
                asm volatile("ldmatrix.sync.aligned.m8n8.x4.shared.b16 {%0,%1,%2,%3}, [%4];"
                             : "=r"(a[i][0]), "=r"(a[i][1]), "=r"(a[i][2]), "=r"(a[i][3])
                             : "r"(addr));
            }
#pragma unroll
            for (int j = 0; j < 4; j++) {
                int r = warp_n * 32 + j * 8 + (lane & 7);
                int c = kk * 16 + (((lane >> 3) & 1) << 3);
                uint32_t addr = bBase + (uint32_t)(r * PITCH + c) * 2;
                asm volatile("ldmatrix.sync.aligned.m8n8.x2.shared.b16 {%0,%1}, [%2];"
                             : "=r"(b[j][0]), "=r"(b[j][1]) : "r"(addr));
            }
#pragma unroll
            for (int i = 0; i < 2; i++)
#pragma unroll
                for (int j = 0; j < 4; j++) {
                    asm volatile(
                        "mma.sync.aligned.m16n8k16.row.col.f32.bf16.bf16.f32 "
                        "{%0,%1,%2,%3}, {%4,%5,%6,%7}, {%8,%9}, {%0,%1,%2,%3};"
                        : "+f"(acc[i][j][0]), "+f"(acc[i][j][1]),
                          "+f"(acc[i][j][2]), "+f"(acc[i][j][3])
                        : "r"(a[i][0]), "r"(a[i][1]), "r"(a[i][2]), "r"(a[i][3]),
                          "r"(b[j][0]), "r"(b[j][1]));
                }
        }
    }

    // direct-fragment epilogue (round-8 proven)
    const int qr = lane >> 2;
    const int qc = (lane & 3) * 2;
#pragma unroll
    for (int i = 0; i < 2; i++) {
#pragma unroll
        for (int j = 0; j < 4; j++) {
            int gc = col0 + warp_n * 32 + j * 8 + qc;
#pragma unroll
            for (int half = 0; half < 2; half++) {
                int gr = row0 + warp_m * 32 + i * 16 + qr + half * 8;
                float v0 = acc[i][j][half * 2 + 0];
                float v1 = acc[i][j][half * 2 + 1];
                if (flags & GF_BIAS) { v0 += bias[gc]; v1 += bias[gc + 1]; }
                if (flags & GF_RES) {
                    const float* rp = res + (size_t)gr * N + gc;
                    v0 += rp[0]; v1 += rp[1];
                }
                if (flags & GF_RELU) { v0 = fmaxf(v0, 0.f); v1 = fmaxf(v1, 0.f); }
                if (outf) *(float2*)(outf + (size_t)gr * N + gc) = make_float2(v0, v1);
                if (outb) {
                    __nv_bfloat162 p = __floats2bfloat162_rn(v0, v1);
                    *(__nv_bfloat162*)(outb + (size_t)gr * N + gc) = p;
                }
            }
        }
    }
}

// ---------------- proj GEMM + residual + LN2 fused, PBM=16 (grid-limited fix) ----------------
// 16x256 block tile (full rows), BK=32, 3-stage pipeline; 512 blocks.
// All 8 warps share the 16-row m-fragment; each warp owns 32 N-cols.
#define PBM 16
#define PSTG 3
#define P_A_BYTES  1280              // 16*40*2
#define P_STAGE    21760             // 1280 + 256*40*2
#define PROJ_DSM   (PSTG * P_STAGE)  // 65280
#define PST_PITCH  264

__global__ __launch_bounds__(256) void proj_ln_kernel(
    const __nv_bfloat16* __restrict__ A, const __nv_bfloat16* __restrict__ Bt,
    const float* __restrict__ bias, const float* __restrict__ res,
    const float* __restrict__ g2, const float* __restrict__ be2,
    float* __restrict__ x2, __nv_bfloat16* __restrict__ h2b)
{
    extern __shared__ __align__(16) char dsm[];

    const int tid  = threadIdx.x;
    const int wid  = tid >> 5;     // warp_n = wid: 32 cols each
    const int lane = tid & 31;
    const int row0 = blockIdx.x * PBM;

    const uint32_t sbase = smem_u32(dsm);
    const int l_row = tid >> 2;          // 0..63
    const int l_c8  = (tid & 3) << 3;

    float acc[4][4];
#pragma unroll
    for (int j = 0; j < 4; j++)
#pragma unroll
        for (int r = 0; r < 4; r++) acc[j][r] = 0.f;

    const int nch = C_ / BK;   // 8

    // prologue: chunks 0,1
#pragma unroll
    for (int p = 0; p < 2; p++) {
        int k0 = p * BK;
        uint32_t baseA = sbase + (uint32_t)(p * P_STAGE);
        uint32_t baseB = baseA + P_A_BYTES;
        if (tid < 64)
            CP_ASYNC16(baseA + (uint32_t)((tid >> 2) * PITCH + l_c8) * 2,
                       A + (size_t)(row0 + (tid >> 2)) * C_ + k0 + l_c8);
#pragma unroll
        for (int v = 0; v < 4; v++) {
            int brow = l_row + v * 64;
            CP_ASYNC16(baseB + (uint32_t)(brow * PITCH + l_c8) * 2,
                       Bt + (size_t)brow * C_ + k0 + l_c8);
        }
        CP_COMMIT();
    }

    for (int ch = 0; ch < nch; ch++) {
        if (ch + 1 < nch) { CP_WAIT(1); } else { CP_WAIT(0); }
        __syncthreads();

        if (ch + 2 < nch) {
            int k0 = (ch + 2) * BK;
            int nb = (ch + 2) % PSTG;
            uint32_t baseA = sbase + (uint32_t)(nb * P_STAGE);
            uint32_t baseB = baseA + P_A_BYTES;
            if (tid < 64)
                CP_ASYNC16(baseA + (uint32_t)((tid >> 2) * PITCH + l_c8) * 2,
                           A + (size_t)(row0 + (tid >> 2)) * C_ + k0 + l_c8);
#pragma unroll
            for (int v = 0; v < 4; v++) {
                int brow = l_row + v * 64;
                CP_ASYNC16(baseB + (uint32_t)(brow * PITCH + l_c8) * 2,
                           Bt + (size_t)brow * C_ + k0 + l_c8);
            }
            CP_COMMIT();
        }

        int buf = ch % PSTG;
        uint32_t aBase = sbase + (uint32_t)(buf * P_STAGE);
        uint32_t bBase = aBase + P_A_BYTES;

#pragma unroll
        for (int kk = 0; kk < 2; kk++) {
            uint32_t a[4];
            {
                int r = lane & 15;
                int c = kk * 16 + ((lane >> 4) << 3);
                uint32_t addr = aBase + (uint32_t)(r * PITCH + c) * 2;
                asm volatile("ldmatrix.sync.aligned.m8n8.x4.shared.b16 {%0,%1,%2,%3}, [%4];"
                             : "=r"(a[0]), "=r"(a[1]), "=r"(a[2]), "=r"(a[3]) : "r"(addr));
            }
#pragma unroll
            for (int j = 0; j < 4; j++) {
                uint32_t b0, b1;
                int r = wid * 32 + j * 8 + (lane & 7);
                int c = kk * 16 + (((lane >> 3) & 1) << 3);
                uint32_t addr = bBase + (uint32_t)(r * PITCH + c) * 2;
                asm volatile("ldmatrix.sync.aligned.m8n8.x2.shared.b16 {%0,%1}, [%2];"
                             : "=r"(b0), "=r"(b1) : "r"(addr));
                asm volatile(
                    "mma.sync.aligned.m16n8k16.row.col.f32.bf16.bf16.f32 "
                    "{%0,%1,%2,%3}, {%4,%5,%6,%7}, {%8,%9}, {%0,%1,%2,%3};"
                    : "+f"(acc[j][0]), "+f"(acc[j][1]), "+f"(acc[j][2]), "+f"(acc[j][3])
                    : "r"(a[0]), "r"(a[1]), "r"(a[2]), "r"(a[3]), "r"(b0), "r"(b1));
            }
        }
    }

    // epilogue: stage 16x256 tile in smem (stage-0 region; disjoint from last-read stage 1)
    __syncthreads();
    float* st = (float*)dsm;   // 16 x 264 fp32 = 16896 B

    const int qr = lane >> 2;
    const int qc = (lane & 3) * 2;
#pragma unroll
    for (int j = 0; j < 4; j++) {
        int c = wid * 32 + j * 8 + qc;
#pragma unroll
        for (int half = 0; half < 2; half++) {
            int r = qr + half * 8;
            st[r * PST_PITCH + c]     = acc[j][half * 2 + 0];
            st[r * PST_PITCH + c + 1] = acc[j][half * 2 + 1];
        }
    }
    __syncthreads();

    // 8 warps x 2 rows: residual + LN
#pragma unroll
    for (int k = 0; k < 2; k++) {
        int row = wid * 2 + k;
        int gr  = row0 + row;
        float v[8], s = 0.f;
#pragma unroll
        for (int i = 0; i < 8; i++) {
            int c = lane + 32 * i;
            v[i] = st[row * PST_PITCH + c] + bias[c] + res[(size_t)gr * C_ + c];
            s += v[i];
        }
#pragma unroll
        for (int o = 16; o > 0; o >>= 1) s += __shfl_xor_sync(0xffffffffu, s, o);
        float mu = s * (1.f / C_);
        float var = 0.f;
#pragma unroll
        for (int i = 0; i < 8; i++) { float d = v[i] - mu; var += d * d; }
#pragma unroll
        for (int o = 16; o > 0; o >>= 1) var += __shfl_xor_sync(0xffffffffu, var, o);
        float rstd = rsqrtf(var * (1.f / C_) + EPS_);
#pragma unroll
        for (int i = 0; i < 8; i++) {
            int c = lane + 32 * i;
            x2[(size_t)gr * C_ + c] = v[i];
            h2b[(size_t)gr * C_ + c] =
                __float2bfloat16((v[i] - mu) * rstd * g2[c] + be2[c]);
        }
    }
}

// ---------------- flash attention, double-buffered cp.async K/V ----------------
#define APITCH 24

__global__ __launch_bounds__(128) void fattn_kernel(
    const __nv_bfloat16* __restrict__ qkv, __nv_bfloat16* __restrict__ out)
{
    __shared__ __align__(16) __nv_bfloat16 Qs[64 * APITCH];
    __shared__ __align__(16) __nv_bfloat16 Ks[2][64 * APITCH];
    __shared__ __align__(16) __nv_bfloat16 Vs[2][64 * APITCH];

    const int qb = blockIdx.x;
    const int b  = blockIdx.y >> 4;
    const int h  = blockIdx.y & 15;
    const int tid = threadIdx.x, wm = tid >> 5, lane = tid & 31;
    const int g = lane >> 2, tig = lane & 3;
    const int LD = 3 * C_;
    const size_t base = (size_t)b * T_ * LD;

    const int l_row = tid >> 1, l_half = tid & 1;

    {
        const __nv_bfloat16* src = qkv + base + (size_t)(qb * 64 + l_row) * LD + h * D_ + l_half * 8;
        uint4 u = *(const uint4*)src;
        __nv_bfloat16 tmp[8]; *(uint4*)&tmp[0] = u;
#pragma unroll
        for (int i = 0; i < 8; i++)
            Qs[l_row * APITCH + l_half * 8 + i] =
                __float2bfloat16(__bfloat162float(tmp[i]) * QSCALE_);
        const uint4 ones_vec = make_uint4(0x00003F80u, 0u, 0u, 0u);
        *(uint4*)&Vs[l_half][l_row * APITCH + 16] = ones_vec;
    }

    {
        const __nv_bfloat16* ksrc = qkv + base + (size_t)l_row * LD + C_ + h * D_ + l_half * 8;
        CP_ASYNC16(smem_u32(&Ks[0][l_row * APITCH + l_half * 8]), ksrc);
        CP_ASYNC16(smem_u32(&Vs[0][l_row * APITCH + l_half * 8]), ksrc + C_);
        CP_COMMIT();
    }
    __syncthreads();

    uint32_t qa[4];
    {
        int r = wm * 16 + (lane & 15);
        int c = (lane >> 4) << 3;
        uint32_t addr = smem_u32(&Qs[r * APITCH + c]);
        asm volatile("ldmatrix.sync.aligned.m8n8.x4.shared.b16 {%0,%1,%2,%3}, [%4];"
                     : "=r"(qa[0]), "=r"(qa[1]), "=r"(qa[2]), "=r"(qa[3]) : "r"(addr));
    }

    float o[3][4];
#pragma unroll
    for (int n = 0; n < 3; n++)
#pragma unroll
        for (int r = 0; r < 4; r++) o[n][r] = 0.f;

    for (int kt = 0; kt <= qb; kt++) {
        CP_WAIT(0);
        __syncthreads();

        if (kt < qb) {
            const __nv_bfloat16* ksrc = qkv + base + (size_t)((kt + 1) * 64 + l_row) * LD + C_ + h * D_ + l_half * 8;
            int nb = (kt + 1) & 1;
            CP_ASYNC16(smem_u32(&Ks[nb][l_row * APITCH + l_half * 8]), ksrc);
            CP_ASYNC16(smem_u32(&Vs[nb][l_row * APITCH + l_half * 8]), ksrc + C_);
            CP_COMMIT();
        }

        const __nv_bfloat16* Kb = Ks[kt & 1];
        const __nv_bfloat16* Vb = Vs[kt & 1];

        float s[8][4];
#pragma unroll
        for (int f = 0; f < 8; f++) {
            uint32_t b0, b1;
            int r = f * 8 + (lane & 7);
            int c = ((lane >> 3) & 1) << 3;
            uint32_t addr = smem_u32(&Kb[r * APITCH + c]);
            asm volatile("ldmatrix.sync.aligned.m8n8.x2.shared.b16 {%0,%1}, [%2];"
                         : "=r"(b0), "=r"(b1) : "r"(addr));
            s[f][0] = s[f][1] = s[f][2] = s[f][3] = 0.f;
            asm volatile(
                "mma.sync.aligned.m16n8k16.row.col.f32.bf16.bf16.f32 "
                "{%0,%1,%2,%3}, {%4,%5,%6,%7}, {%8,%9}, {%0,%1,%2,%3};"
                : "+f"(s[f][0]), "+f"(s[f][1]), "+f"(s[f][2]), "+f"(s[f][3])
                : "r"(qa[0]), "r"(qa[1]), "r"(qa[2]), "r"(qa[3]), "r"(b0), "r"(b1));
        }

        if (kt == qb) {
            int q0 = wm * 16 + g, q1 = q0 + 8;
#pragma unroll
            for (int f = 0; f < 8; f++) {
                int k0 = f * 8 + 2 * tig;
                if (k0     > q0) s[f][0] = -1e30f;
                if (k0 + 1 > q0) s[f][1] = -1e30f;
                if (k0     > q1) s[f][2] = -1e30f;
                if (k0 + 1 > q1) s[f][3] = -1e30f;
            }
        }

        uint32_t pa[8][2];
#pragma unroll
        for (int f = 0; f < 8; f++) {
            float p0 = ex2f(s[f][0]), p1 = ex2f(s[f][1]);
            float p2 = ex2f(s[f][2]), p3 = ex2f(s[f][3]);
            __nv_bfloat162 u = __floats2bfloat162_rn(p0, p1);
            __nv_bfloat162 w = __floats2bfloat162_rn(p2, p3);
            pa[f][0] = *(uint32_t*)&u;
            pa[f][1] = *(uint32_t*)&w;
        }

#pragma unroll
        for (int j2 = 0; j2 < 4; j2++) {
            int vr = j2 * 16 + (lane & 15);
#pragma unroll
            for (int n = 0; n < 3; n++) {
                uint32_t b0, b1;
                uint32_t addr = smem_u32(&Vb[vr * APITCH + n * 8]);
                asm volatile("ldmatrix.sync.aligned.m8n8.x2.trans.shared.b16 {%0,%1}, [%2];"
                             : "=r"(b0), "=r"(b1) : "r"(addr));
                asm volatile(
                    "mma.sync.aligned.m16n8k16.row.col.f32.bf16.bf16.f32 "
                    "{%0,%1,%2,%3}, {%4,%5,%6,%7}, {%8,%9}, {%0,%1,%2,%3};"
                    : "+f"(o[n][0]), "+f"(o[n][1]), "+f"(o[n][2]), "+f"(o[n][3])
                    : "r"(pa[2*j2][0]), "r"(pa[2*j2][1]),
                      "r"(pa[2*j2+1][0]), "r"(pa[2*j2+1][1]),
                      "r"(b0), "r"(b1));
            }
        }
    }

    float l0 = __shfl_sync(0xffffffffu, o[2][0], lane & ~3);
    float l1 = __shfl_sync(0xffffffffu, o[2][2], lane & ~3);
    float inv0 = 1.f / l0, inv1 = 1.f / l1;

    int gr0 = qb * 64 + wm * 16 + g;
    int gr1 = gr0 + 8;
#pragma unroll
    for (int n = 0; n < 2; n++) {
        int gc = h * D_ + n * 8 + 2 * tig;
        __nv_bfloat162 p0 = __floats2bfloat162_rn(o[n][0] * inv0, o[n][1] * inv0);
        __nv_bfloat162 p1 = __floats2bfloat162_rn(o[n][2] * inv1, o[n][3] * inv1);
        *(__nv_bfloat162*)(out + (size_t)(b * T_ + gr0) * C_ + gc) = p0;
        *(__nv_bfloat162*)(out + (size_t)(b * T_ + gr1) * C_ + gc) = p1;
    }
}

// ---------------- host ----------------
extern "C" void kernel_launch(void* const* d_in, const int* in_sizes, int n_in,
                              void* d_out, int out_size)
{
    const float* x   = (const float*)d_in[0];
    const float* Wq  = (const float*)d_in[1];
    const float* Wk  = (const float*)d_in[2];
    const float* Wv  = (const float*)d_in[3];
    const float* Wp  = (const float*)d_in[4];
    const float* bp  = (const float*)d_in[5];
    const float* W1  = (const float*)d_in[6];
    const float* b1  = (const float*)d_in[7];
    const float* W2  = (const float*)d_in[8];
    const float* b2  = (const float*)d_in[9];
    const float* g1  = (const float*)d_in[10];
    const float* be1 = (const float*)d_in[11];
    const float* g2  = (const float*)d_in[12];
    const float* be2 = (const float*)d_in[13];
    float* out = (float*)d_out;

    __nv_bfloat16 *h1b, *attb, *h2b, *h3b, *qkvb, *wqkvt, *wpt, *w1t, *w2t;
    float *x2;
    cudaGetSymbolAddress((void**)&h1b,   g_h1b);
    cudaGetSymbolAddress((void**)&attb,  g_attb);
    cudaGetSymbolAddress((void**)&h2b,   g_h2b);
    cudaGetSymbolAddress((void**)&h3b,   g_h3b);
    cudaGetSymbolAddress((void**)&qkvb,  g_qkvb);
    cudaGetSymbolAddress((void**)&x2,    g_x2);
    cudaGetSymbolAddress((void**)&wqkvt, g_wqkvt);
    cudaGetSymbolAddress((void**)&wpt,   g_wpt);
    cudaGetSymbolAddress((void**)&w1t,   g_w1t);
    cudaGetSymbolAddress((void**)&w2t,   g_w2t);

    cudaFuncSetAttribute(mma_gemm, cudaFuncAttributeMaxDynamicSharedMemorySize, GEMM_DSM);
    cudaFuncSetAttribute(proj_ln_kernel, cudaFuncAttributeMaxDynamicSharedMemorySize, PROJ_DSM);

    // prep: weight transposes + ln1 in one launch
    prep_kernel<<<768 + M_/8, 256>>>(Wq, Wk, Wv, Wp, W1, W2,
                                     wqkvt, wpt, w1t, w2t,
                                     x, g1, be1, h1b);

    // qkv = h1 @ [Wq|Wk|Wv] (bf16 out)
    mma_gemm<<<dim3(6, M_/BM), 256, GEMM_DSM>>>(h1b, wqkvt, nullptr, nullptr,
                                                nullptr, qkvb, 3*C_, C_, 0);
    // flash attention -> attb bf16
    fattn_kernel<<<dim3(T_/64, B_*H_), 128>>>(qkvb, attb);

    // x2 = x + attb @ Wp^T + bp ; h2 = LN(x2)   (fused, 512 blocks)
    proj_ln_kernel<<<M_/PBM, 256, PROJ_DSM>>>(attb, wpt, bp, x, g2, be2, x2, h2b);

    // h3 = relu(h2 @ W1^T + b1)
    mma_gemm<<<dim3(8, M_/BM), 256, GEMM_DSM>>>(h2b, w1t, b1, nullptr,
                                                nullptr, h3b, FF_, C_, GF_BIAS | GF_RELU);
    // out = x2 + h3 @ W2^T + b2
    mma_gemm<<<dim3(2, M_/BM), 256, GEMM_DSM>>>(h3b, w2t, b2, x2,
                                                out, nullptr, C_, FF_, GF_BIAS | GF_RES);
}

// round 13
// speedup vs baseline: 1.0135x; 1.0135x over previous
#include <cuda_runtime.h>
#include <cuda_bf16.h>
#include <math.h>
#include <stdint.h>

// Problem constants
#define B_   8
#define T_   1024
#define C_   256
#define H_   16
#define D_   16
#define M_   (B_ * T_)        // 8192
#define FF_  (4 * C_)         // 1024
#define EPS_ 1e-5f
#define QSCALE_ 0.360673760222f   // 0.25 * log2(e)

// ---------------- scratch ----------------
__device__ __nv_bfloat16 g_h1b [M_ * C_];
__device__ __nv_bfloat16 g_attb[M_ * C_];
__device__ __nv_bfloat16 g_h2b [M_ * C_];
__device__ __nv_bfloat16 g_h3b [M_ * FF_];
__device__ __nv_bfloat16 g_qkvb[M_ * 3 * C_];   // [row, 768]: q|k|v (bf16)
__device__ float         g_x2  [M_ * C_];
__device__ __nv_bfloat16 g_wqkvt[3 * C_ * C_];  // [768, 256]
__device__ __nv_bfloat16 g_wpt  [C_ * C_];
__device__ __nv_bfloat16 g_w1t  [FF_ * C_];
__device__ __nv_bfloat16 g_w2t  [C_ * FF_];

__device__ __forceinline__ uint32_t smem_u32(const void* p) {
    uint32_t a;
    asm("{ .reg .u64 t; cvta.to.shared.u64 t, %1; cvt.u32.u64 %0, t; }" : "=r"(a) : "l"(p));
    return a;
}
__device__ __forceinline__ float ex2f(float x) {
    float y;
    asm("ex2.approx.ftz.f32 %0, %1;" : "=f"(y) : "f"(x));
    return y;
}
#define CP_ASYNC16(dst, src) \
    asm volatile("cp.async.cg.shared.global [%0], [%1], 16;" :: "r"(dst), "l"(src))
#define CP_COMMIT() asm volatile("cp.async.commit_group;" ::: "memory")
#define CP_WAIT(n)  asm volatile("cp.async.wait_group %0;" :: "n"(n) : "memory")

// ---------------- LN body (device) ----------------
__device__ __forceinline__ void ln_row(const float* __restrict__ x, const float* __restrict__ g,
                                       const float* __restrict__ b, __nv_bfloat16* __restrict__ y,
                                       int row, int lane)
{
    const float* xr = x + (size_t)row * C_;
    float v[8], s = 0.f;
#pragma unroll
    for (int i = 0; i < 8; i++) { v[i] = xr[lane + 32 * i]; s += v[i]; }
#pragma unroll
    for (int o = 16; o > 0; o >>= 1) s += __shfl_xor_sync(0xffffffffu, s, o);
    float mu = s * (1.f / C_);
    float var = 0.f;
#pragma unroll
    for (int i = 0; i < 8; i++) { float d = v[i] - mu; var += d * d; }
#pragma unroll
    for (int o = 16; o > 0; o >>= 1) var += __shfl_xor_sync(0xffffffffu, var, o);
    float rstd = rsqrtf(var * (1.f / C_) + EPS_);
    __nv_bfloat16* yr = y + (size_t)row * C_;
#pragma unroll
    for (int i = 0; i < 8; i++) {
        int c = lane + 32 * i;
        yr[c] = __float2bfloat16((v[i] - mu) * rstd * g[c] + b[c]);
    }
}

__global__ void ln_kernel(const float* __restrict__ x, const float* __restrict__ g,
                          const float* __restrict__ b, __nv_bfloat16* __restrict__ y)
{
    int row  = blockIdx.x * 8 + (threadIdx.x >> 5);
    ln_row(x, g, b, y, row, threadIdx.x & 31);
}

// ---------------- prep: weight transposes + ln1, one launch ----------------
__global__ void prep_kernel(const float* __restrict__ Wq, const float* __restrict__ Wk,
                            const float* __restrict__ Wv, const float* __restrict__ Wp,
                            const float* __restrict__ W1, const float* __restrict__ W2,
                            __nv_bfloat16* __restrict__ wqkvt, __nv_bfloat16* __restrict__ wpt,
                            __nv_bfloat16* __restrict__ w1t, __nv_bfloat16* __restrict__ w2t,
                            const float* __restrict__ x, const float* __restrict__ g1,
                            const float* __restrict__ be1, __nv_bfloat16* __restrict__ h1b)
{
    int bid = blockIdx.x;
    if (bid >= 768) {
        int row = (bid - 768) * 8 + (threadIdx.x >> 5);
        ln_row(x, g1, be1, h1b, row, threadIdx.x & 31);
        return;
    }
    __shared__ float t[32][33];
    const float* in; __nv_bfloat16* out; int K, N, tt;
    if (bid < 192)       { int w = bid >> 6; tt = bid & 63;
                           in = (w == 0) ? Wq : (w == 1) ? Wk : Wv;
                           out = wqkvt + w * C_ * C_; K = C_; N = C_; }
    else if (bid < 256)  { tt = bid - 192; in = Wp; out = wpt; K = C_;  N = C_;  }
    else if (bid < 512)  { tt = bid - 256; in = W1; out = w1t; K = C_;  N = FF_; }
    else                 { tt = bid - 512; in = W2; out = w2t; K = FF_; N = C_;  }
    int ntx = N >> 5;
    int n0 = (tt % ntx) * 32, k0 = (tt / ntx) * 32;
    int tx = threadIdx.x & 31, ty = threadIdx.x >> 5;
#pragma unroll
    for (int i = ty; i < 32; i += 8)
        t[i][tx] = in[(size_t)(k0 + i) * N + n0 + tx];
    __syncthreads();
#pragma unroll
    for (int i = ty; i < 32; i += 8)
        out[(size_t)(n0 + i) * K + k0 + tx] = __float2bfloat16(t[tx][i]);
}

// ---------------- bf16 mma.sync GEMM, 3-stage pipeline, templated on BN ----------------
// 64 x TBN block tile, BK=32, 256 threads (2x4 warps, 32 x TBN/4 per warp).
#define GF_BIAS 1
#define GF_RELU 2
#define GF_RES  4
#define BM 64
#define BK 32
#define PITCH 40
#define STG 3

template <int TBN>
__global__ __launch_bounds__(256, 2) void mma_gemm(
    const __nv_bfloat16* __restrict__ A, const __nv_bfloat16* __restrict__ Bt,
    const float* __restrict__ bias, const float* __restrict__ res,
    float* __restrict__ outf, __nv_bfloat16* __restrict__ outb,
    int N, int K, int flags)
{
    constexpr int NFR = TBN / 32;       // n-fragments of 8 per warp (4 for 128, 2 for 64)
    constexpr int BROWS = TBN / 64;     // B-load row groups (2 for 128, 1 for 64)

    __shared__ __nv_bfloat16 sA[STG][BM * PITCH];
    __shared__ __nv_bfloat16 sB[STG][TBN * PITCH];

    const int tid  = threadIdx.x;
    const int wid  = tid >> 5;
    const int lane = tid & 31;
    const int warp_m = wid >> 2;        // 0..1 -> 32 rows each
    const int warp_n = wid & 3;         // 0..3 -> TBN/4 cols each
    const int row0 = blockIdx.y * BM;
    const int col0 = blockIdx.x * TBN;

    const uint32_t saA = smem_u32(sA);
    const uint32_t saB = smem_u32(sB);

    const int l_row = tid >> 2;          // 0..63
    const int l_c8  = (tid & 3) << 3;    // 0,8,16,24

    float acc[2][NFR][4];
#pragma unroll
    for (int i = 0; i < 2; i++)
#pragma unroll
        for (int j = 0; j < NFR; j++)
#pragma unroll
            for (int r = 0; r < 4; r++) acc[i][j][r] = 0.f;

    const int nch = K / BK;

    // prologue: issue chunks 0 and 1
#pragma unroll
    for (int p = 0; p < 2; p++) {
        int k0 = p * BK;
        uint32_t baseA = saA + (uint32_t)(p * BM * PITCH) * 2;
        uint32_t baseB = saB + (uint32_t)(p * TBN * PITCH) * 2;
        CP_ASYNC16(baseA + (uint32_t)(l_row * PITCH + l_c8) * 2,
                   A + (size_t)(row0 + l_row) * K + k0 + l_c8);
#pragma unroll
        for (int v = 0; v < BROWS; v++) {
            int brow = l_row + v * 64;
            CP_ASYNC16(baseB + (uint32_t)(brow * PITCH + l_c8) * 2,
                       Bt + (size_t)(col0 + brow) * K + k0 + l_c8);
        }
        CP_COMMIT();
    }

    for (int ch = 0; ch < nch; ch++) {
        if (ch + 1 < nch) { CP_WAIT(1); } else { CP_WAIT(0); }
        __syncthreads();   // stage (ch+2)%STG last read at iter ch-1 -> safe to refill

        if (ch + 2 < nch) {
            int k0 = (ch + 2) * BK;
            int nb = (ch + 2) % STG;
            uint32_t baseA = saA + (uint32_t)(nb * BM * PITCH) * 2;
            uint32_t baseB = saB + (uint32_t)(nb * TBN * PITCH) * 2;
            CP_ASYNC16(baseA + (uint32_t)(l_row * PITCH + l_c8) * 2,
                       A + (size_t)(row0 + l_row) * K + k0 + l_c8);
#pragma unroll
            for (int v = 0; v < BROWS; v++) {
                int brow = l_row + v * 64;
                CP_ASYNC16(baseB + (uint32_t)(brow * PITCH + l_c8) * 2,
                           Bt + (size_t)(col0 + brow) * K + k0 + l_c8);
            }
            CP_COMMIT();
        }

        int buf = ch % STG;
        uint32_t aBase = saA + (uint32_t)(buf * BM * PITCH) * 2;
        uint32_t bBase = saB + (uint32_t)(buf * TBN * PITCH) * 2;

#pragma unroll
        for (int kk = 0; kk < 2; kk++) {
            uint32_t a[2][4], b[NFR][2];
#pragma unroll
            for (int i = 0; i < 2; i++) {
                int r = warp_m * 32 + i * 16 + (lane & 15);
                int c = kk * 16 + ((lane >> 4) << 3);
                uint32_t addr = aBase + (uint32_t)(r * PITCH + c) * 2;
                asm volatile("ldmatrix.sync.aligned.m8n8.x4.shared.b16 {%0,%1,%2,%3}, [%4];"
                             : "=r"(a[i][0]), "=r"(a[i][1]), "=r"(a[i][2]), "=r"(a[i][3])
                             : "r"(addr));
            }
#pragma unroll
            for (int j = 0; j < NFR; j++) {
                int r = warp_n * (TBN / 4) + j * 8 + (lane & 7);
                int c = kk * 16 + (((lane >> 3) & 1) << 3);
                uint32_t addr = bBase + (uint32_t)(r * PITCH + c) * 2;
                asm volatile("ldmatrix.sync.aligned.m8n8.x2.shared.b16 {%0,%1}, [%2];"
                             : "=r"(b[j][0]), "=r"(b[j][1]) : "r"(addr));
            }
#pragma unroll
            for (int i = 0; i < 2; i++)
#pragma unroll
                for (int j = 0; j < NFR; j++) {
                    asm volatile(
                        "mma.sync.aligned.m16n8k16.row.col.f32.bf16.bf16.f32 "
                        "{%0,%1,%2,%3}, {%4,%5,%6,%7}, {%8,%9}, {%0,%1,%2,%3};"
                        : "+f"(acc[i][j][0]), "+f"(acc[i][j][1]),
                          "+f"(acc[i][j][2]), "+f"(acc[i][j][3])
                        : "r"(a[i][0]), "r"(a[i][1]), "r"(a[i][2]), "r"(a[i][3]),
                          "r"(b[j][0]), "r"(b[j][1]));
                }
        }
        __syncthreads();
    }

    // direct-fragment epilogue
    const int qr = lane >> 2;
    const int qc = (lane & 3) * 2;
#pragma unroll
    for (int i = 0; i < 2; i++) {
#pragma unroll
        for (int j = 0; j < NFR; j++) {
            int gc = col0 + warp_n * (TBN / 4) + j * 8 + qc;
#pragma unroll
            for (int half = 0; half < 2; half++) {
                int gr = row0 + warp_m * 32 + i * 16 + qr + half * 8;
                float v0 = acc[i][j][half * 2 + 0];
                float v1 = acc[i][j][half * 2 + 1];
                if (flags & GF_BIAS) { v0 += bias[gc]; v1 += bias[gc + 1]; }
                if (flags & GF_RES) {
                    const float* rp = res + (size_t)gr * N + gc;
                    v0 += rp[0]; v1 += rp[1];
                }
                if (flags & GF_RELU) { v0 = fmaxf(v0, 0.f); v1 = fmaxf(v1, 0.f); }
                if (outf) *(float2*)(outf + (size_t)gr * N + gc) = make_float2(v0, v1);
                if (outb) {
                    __nv_bfloat162 p = __floats2bfloat162_rn(v0, v1);
                    *(__nv_bfloat162*)(outb + (size_t)gr * N + gc) = p;
                }
            }
        }
    }
}

// ---------------- flash attention, double-buffered cp.async K/V ----------------
#define APITCH 24

__global__ __launch_bounds__(128) void fattn_kernel(
    const __nv_bfloat16* __restrict__ qkv, __nv_bfloat16* __restrict__ out)
{
    __shared__ __align__(16) __nv_bfloat16 Qs[64 * APITCH];
    __shared__ __align__(16) __nv_bfloat16 Ks[2][64 * APITCH];
    __shared__ __align__(16) __nv_bfloat16 Vs[2][64 * APITCH];

    const int qb = blockIdx.x;
    const int b  = blockIdx.y >> 4;
    const int h  = blockIdx.y & 15;
    const int tid = threadIdx.x, wm = tid >> 5, lane = tid & 31;
    const int g = lane >> 2, tig = lane & 3;
    const int LD = 3 * C_;
    const size_t base = (size_t)b * T_ * LD;

    const int l_row = tid >> 1, l_half = tid & 1;

    {
        const __nv_bfloat16* src = qkv + base + (size_t)(qb * 64 + l_row) * LD + h * D_ + l_half * 8;
        uint4 u = *(const uint4*)src;
        __nv_bfloat16 tmp[8]; *(uint4*)&tmp[0] = u;
#pragma unroll
        for (int i = 0; i < 8; i++)
            Qs[l_row * APITCH + l_half * 8 + i] =
                __float2bfloat16(__bfloat162float(tmp[i]) * QSCALE_);
        const uint4 ones_vec = make_uint4(0x00003F80u, 0u, 0u, 0u);
        *(uint4*)&Vs[l_half][l_row * APITCH + 16] = ones_vec;
    }

    {
        const __nv_bfloat16* ksrc = qkv + base + (size_t)l_row * LD + C_ + h * D_ + l_half * 8;
        CP_ASYNC16(smem_u32(&Ks[0][l_row * APITCH + l_half * 8]), ksrc);
        CP_ASYNC16(smem_u32(&Vs[0][l_row * APITCH + l_half * 8]), ksrc + C_);
        CP_COMMIT();
    }
    __syncthreads();

    uint32_t qa[4];
    {
        int r = wm * 16 + (lane & 15);
        int c = (lane >> 4) << 3;
        uint32_t addr = smem_u32(&Qs[r * APITCH + c]);
        asm volatile("ldmatrix.sync.aligned.m8n8.x4.shared.b16 {%0,%1,%2,%3}, [%4];"
                     : "=r"(qa[0]), "=r"(qa[1]), "=r"(qa[2]), "=r"(qa[3]) : "r"(addr));
    }

    float o[3][4];
#pragma unroll
    for (int n = 0; n < 3; n++)
#pragma unroll
        for (int r = 0; r < 4; r++) o[n][r] = 0.f;

    for (int kt = 0; kt <= qb; kt++) {
        CP_WAIT(0);
        __syncthreads();

        if (kt < qb) {
            const __nv_bfloat16* ksrc = qkv + base + (size_t)((kt + 1) * 64 + l_row) * LD + C_ + h * D_ + l_half * 8;
            int nb = (kt + 1) & 1;
            CP_ASYNC16(smem_u32(&Ks[nb][l_row * APITCH + l_half * 8]), ksrc);
            CP_ASYNC16(smem_u32(&Vs[nb][l_row * APITCH + l_half * 8]), ksrc + C_);
            CP_COMMIT();
        }

        const __nv_bfloat16* Kb = Ks[kt & 1];
        const __nv_bfloat16* Vb = Vs[kt & 1];

        float s[8][4];
#pragma unroll
        for (int f = 0; f < 8; f++) {
            uint32_t b0, b1;
            int r = f * 8 + (lane & 7);
            int c = ((lane >> 3) & 1) << 3;
            uint32_t addr = smem_u32(&Kb[r * APITCH + c]);
            asm volatile("ldmatrix.sync.aligned.m8n8.x2.shared.b16 {%0,%1}, [%2];"
                         : "=r"(b0), "=r"(b1) : "r"(addr));
            s[f][0] = s[f][1] = s[f][2] = s[f][3] = 0.f;
            asm volatile(
                "mma.sync.aligned.m16n8k16.row.col.f32.bf16.bf16.f32 "
                "{%0,%1,%2,%3}, {%4,%5,%6,%7}, {%8,%9}, {%0,%1,%2,%3};"
                : "+f"(s[f][0]), "+f"(s[f][1]), "+f"(s[f][2]), "+f"(s[f][3])
                : "r"(qa[0]), "r"(qa[1]), "r"(qa[2]), "r"(qa[3]), "r"(b0), "r"(b1));
        }

        if (kt == qb) {
            int q0 = wm * 16 + g, q1 = q0 + 8;
#pragma unroll
            for (int f = 0; f < 8; f++) {
                int k0 = f * 8 + 2 * tig;
                if (k0     > q0) s[f][0] = -1e30f;
                if (k0 + 1 > q0) s[f][1] = -1e30f;
                if (k0     > q1) s[f][2] = -1e30f;
                if (k0 + 1 > q1) s[f][3] = -1e30f;
            }
        }

        uint32_t pa[8][2];
#pragma unroll
        for (int f = 0; f < 8; f++) {
            float p0 = ex2f(s[f][0]), p1 = ex2f(s[f][1]);
            float p2 = ex2f(s[f][2]), p3 = ex2f(s[f][3]);
            __nv_bfloat162 u = __floats2bfloat162_rn(p0, p1);
            __nv_bfloat162 w = __floats2bfloat162_rn(p2, p3);
            pa[f][0] = *(uint32_t*)&u;
            pa[f][1] = *(uint32_t*)&w;
        }

#pragma unroll
        for (int j2 = 0; j2 < 4; j2++) {
            int vr = j2 * 16 + (lane & 15);
#pragma unroll
            for (int n = 0; n < 3; n++) {
                uint32_t b0, b1;
                uint32_t addr = smem_u32(&Vb[vr * APITCH + n * 8]);
                asm volatile("ldmatrix.sync.aligned.m8n8.x2.trans.shared.b16 {%0,%1}, [%2];"
                             : "=r"(b0), "=r"(b1) : "r"(addr));
                asm volatile(
                    "mma.sync.aligned.m16n8k16.row.col.f32.bf16.bf16.f32 "
                    "{%0,%1,%2,%3}, {%4,%5,%6,%7}, {%8,%9}, {%0,%1,%2,%3};"
                    : "+f"(o[n][0]), "+f"(o[n][1]), "+f"(o[n][2]), "+f"(o[n][3])
                    : "r"(pa[2*j2][0]), "r"(pa[2*j2][1]),
                      "r"(pa[2*j2+1][0]), "r"(pa[2*j2+1][1]),
                      "r"(b0), "r"(b1));
            }
        }
    }

    float l0 = __shfl_sync(0xffffffffu, o[2][0], lane & ~3);
    float l1 = __shfl_sync(0xffffffffu, o[2][2], lane & ~3);
    float inv0 = 1.f / l0, inv1 = 1.f / l1;

    int gr0 = qb * 64 + wm * 16 + g;
    int gr1 = gr0 + 8;
#pragma unroll
    for (int n = 0; n < 2; n++) {
        int gc = h * D_ + n * 8 + 2 * tig;
        __nv_bfloat162 p0 = __floats2bfloat162_rn(o[n][0] * inv0, o[n][1] * inv0);
        __nv_bfloat162 p1 = __floats2bfloat162_rn(o[n][2] * inv1, o[n][3] * inv1);
        *(__nv_bfloat162*)(out + (size_t)(b * T_ + gr0) * C_ + gc) = p0;
        *(__nv_bfloat162*)(out + (size_t)(b * T_ + gr1) * C_ + gc) = p1;
    }
}

// ---------------- host ----------------
extern "C" void kernel_launch(void* const* d_in, const int* in_sizes, int n_in,
                              void* d_out, int out_size)
{
    const float* x   = (const float*)d_in[0];
    const float* Wq  = (const float*)d_in[1];
    const float* Wk  = (const float*)d_in[2];
    const float* Wv  = (const float*)d_in[3];
    const float* Wp  = (const float*)d_in[4];
    const float* bp  = (const float*)d_in[5];
    const float* W1  = (const float*)d_in[6];
    const float* b1  = (const float*)d_in[7];
    const float* W2  = (const float*)d_in[8];
    const float* b2  = (const float*)d_in[9];
    const float* g1  = (const float*)d_in[10];
    const float* be1 = (const float*)d_in[11];
    const float* g2  = (const float*)d_in[12];
    const float* be2 = (const float*)d_in[13];
    float* out = (float*)d_out;

    __nv_bfloat16 *h1b, *attb, *h2b, *h3b, *qkvb, *wqkvt, *wpt, *w1t, *w2t;
    float *x2;
    cudaGetSymbolAddress((void**)&h1b,   g_h1b);
    cudaGetSymbolAddress((void**)&attb,  g_attb);
    cudaGetSymbolAddress((void**)&h2b,   g_h2b);
    cudaGetSymbolAddress((void**)&h3b,   g_h3b);
    cudaGetSymbolAddress((void**)&qkvb,  g_qkvb);
    cudaGetSymbolAddress((void**)&x2,    g_x2);
    cudaGetSymbolAddress((void**)&wqkvt, g_wqkvt);
    cudaGetSymbolAddress((void**)&wpt,   g_wpt);
    cudaGetSymbolAddress((void**)&w1t,   g_w1t);
    cudaGetSymbolAddress((void**)&w2t,   g_w2t);

    // prep: weight transposes + ln1 in one launch
    prep_kernel<<<768 + M_/8, 256>>>(Wq, Wk, Wv, Wp, W1, W2,
                                     wqkvt, wpt, w1t, w2t,
                                     x, g1, be1, h1b);

    // qkv = h1 @ [Wq|Wk|Wv] (bf16 out), BN=128
    mma_gemm<128><<<dim3(6, M_/BM), 256>>>(h1b, wqkvt, nullptr, nullptr,
                                           nullptr, qkvb, 3*C_, C_, 0);
    // flash attention -> attb bf16
    fattn_kernel<<<dim3(T_/64, B_*H_), 128>>>(qkvb, attb);

    // x2 = x + attb @ Wp^T + bp, BN=64 -> 512 blocks
    mma_gemm<64><<<dim3(4, M_/BM), 256>>>(attb, wpt, bp, x,
                                          x2, nullptr, C_, C_, GF_BIAS | GF_RES);
    // ln2 -> h2 bf16
    ln_kernel<<<M_/8, 256>>>(x2, g2, be2, h2b);

    // h3 = relu(h2 @ W1^T + b1), BN=128
    mma_gemm<128><<<dim3(8, M_/BM), 256>>>(h2b, w1t, b1, nullptr,
                                           nullptr, h3b, FF_, C_, GF_BIAS | GF_RELU);
    // out = x2 + h3 @ W2^T + b2, BN=64 -> 512 blocks
    mma_gemm<64><<<dim3(4, M_/BM), 256>>>(h3b, w2t, b2, x2,
                                          out, nullptr, C_, FF_, GF_BIAS | GF_RES);
}

// round 14
// speedup vs baseline: 1.1178x; 1.1030x over previous
#include <cuda_runtime.h>
#include <cuda_bf16.h>
#include <math.h>
#include <stdint.h>

// Problem constants
#define B_   8
#define T_   1024
#define C_   256
#define H_   16
#define D_   16
#define M_   (B_ * T_)        // 8192
#define FF_  (4 * C_)         // 1024
#define EPS_ 1e-5f
#define QSCALE_ 0.360673760222f   // 0.25 * log2(e)

// ---------------- scratch ----------------
__device__ __nv_bfloat16 g_h1b [M_ * C_];
__device__ __nv_bfloat16 g_attb[M_ * C_];
__device__ __nv_bfloat16 g_h2b [M_ * C_];
__device__ __nv_bfloat16 g_h3b [M_ * FF_];
__device__ __nv_bfloat16 g_qkvb[M_ * 3 * C_];   // [row, 768]: q|k|v (bf16)
__device__ float         g_x2  [M_ * C_];
__device__ __nv_bfloat16 g_wqkvt[3 * C_ * C_];  // [768, 256]
__device__ __nv_bfloat16 g_wpt  [C_ * C_];
__device__ __nv_bfloat16 g_w1t  [FF_ * C_];
__device__ __nv_bfloat16 g_w2t  [C_ * FF_];

__device__ __forceinline__ uint32_t smem_u32(const void* p) {
    uint32_t a;
    asm("{ .reg .u64 t; cvta.to.shared.u64 t, %1; cvt.u32.u64 %0, t; }" : "=r"(a) : "l"(p));
    return a;
}
__device__ __forceinline__ float ex2f(float x) {
    float y;
    asm("ex2.approx.ftz.f32 %0, %1;" : "=f"(y) : "f"(x));
    return y;
}
#define CP_ASYNC16(dst, src) \
    asm volatile("cp.async.cg.shared.global [%0], [%1], 16;" :: "r"(dst), "l"(src))
#define CP_COMMIT() asm volatile("cp.async.commit_group;" ::: "memory")
#define CP_WAIT(n)  asm volatile("cp.async.wait_group %0;" :: "n"(n) : "memory")

// ---------------- LN body (device) ----------------
__device__ __forceinline__ void ln_row(const float* __restrict__ x, const float* __restrict__ g,
                                       const float* __restrict__ b, __nv_bfloat16* __restrict__ y,
                                       int row, int lane)
{
    const float* xr = x + (size_t)row * C_;
    float v[8], s = 0.f;
#pragma unroll
    for (int i = 0; i < 8; i++) { v[i] = xr[lane + 32 * i]; s += v[i]; }
#pragma unroll
    for (int o = 16; o > 0; o >>= 1) s += __shfl_xor_sync(0xffffffffu, s, o);
    float mu = s * (1.f / C_);
    float var = 0.f;
#pragma unroll
    for (int i = 0; i < 8; i++) { float d = v[i] - mu; var += d * d; }
#pragma unroll
    for (int o = 16; o > 0; o >>= 1) var += __shfl_xor_sync(0xffffffffu, var, o);
    float rstd = rsqrtf(var * (1.f / C_) + EPS_);
    __nv_bfloat16* yr = y + (size_t)row * C_;
#pragma unroll
    for (int i = 0; i < 8; i++) {
        int c = lane + 32 * i;
        yr[c] = __float2bfloat16((v[i] - mu) * rstd * g[c] + b[c]);
    }
}

__global__ void ln_kernel(const float* __restrict__ x, const float* __restrict__ g,
                          const float* __restrict__ b, __nv_bfloat16* __restrict__ y)
{
    int row  = blockIdx.x * 8 + (threadIdx.x >> 5);
    ln_row(x, g, b, y, row, threadIdx.x & 31);
}

// ---------------- prep: weight transposes + ln1, one launch ----------------
__global__ void prep_kernel(const float* __restrict__ Wq, const float* __restrict__ Wk,
                            const float* __restrict__ Wv, const float* __restrict__ Wp,
                            const float* __restrict__ W1, const float* __restrict__ W2,
                            __nv_bfloat16* __restrict__ wqkvt, __nv_bfloat16* __restrict__ wpt,
                            __nv_bfloat16* __restrict__ w1t, __nv_bfloat16* __restrict__ w2t,
                            const float* __restrict__ x, const float* __restrict__ g1,
                            const float* __restrict__ be1, __nv_bfloat16* __restrict__ h1b)
{
    int bid = blockIdx.x;
    if (bid >= 768) {
        int row = (bid - 768) * 8 + (threadIdx.x >> 5);
        ln_row(x, g1, be1, h1b, row, threadIdx.x & 31);
        return;
    }
    __shared__ float t[32][33];
    const float* in; __nv_bfloat16* out; int K, N, tt;
    if (bid < 192)       { int w = bid >> 6; tt = bid & 63;
                           in = (w == 0) ? Wq : (w == 1) ? Wk : Wv;
                           out = wqkvt + w * C_ * C_; K = C_; N = C_; }
    else if (bid < 256)  { tt = bid - 192; in = Wp; out = wpt; K = C_;  N = C_;  }
    else if (bid < 512)  { tt = bid - 256; in = W1; out = w1t; K = C_;  N = FF_; }
    else                 { tt = bid - 512; in = W2; out = w2t; K = FF_; N = C_;  }
    int ntx = N >> 5;
    int n0 = (tt % ntx) * 32, k0 = (tt / ntx) * 32;
    int tx = threadIdx.x & 31, ty = threadIdx.x >> 5;
#pragma unroll
    for (int i = ty; i < 32; i += 8)
        t[i][tx] = in[(size_t)(k0 + i) * N + n0 + tx];
    __syncthreads();
#pragma unroll
    for (int i = ty; i < 32; i += 8)
        out[(size_t)(n0 + i) * K + k0 + tx] = __float2bfloat16(t[tx][i]);
}

// ---------------- bf16 mma.sync GEMM, 3-stage pipeline, BK=64 ----------------
// 64x128 block tile, BK=64, 256 threads (2x4 warps, 32x32 per warp), 2 blocks/SM.
#define GF_BIAS 1
#define GF_RELU 2
#define GF_RES  4
#define BM 64
#define BN 128
#define BK 64
#define PITCH 72                      // 64 + 8 pad bf16 per row
#define STG 3
#define A_BYTES (BM * PITCH * 2)      // 9216
#define STAGE_BYTES ((BM + BN) * PITCH * 2)   // 27648
#define GEMM_DSM (STG * STAGE_BYTES)  // 82944

__global__ __launch_bounds__(256) void mma_gemm(
    const __nv_bfloat16* __restrict__ A, const __nv_bfloat16* __restrict__ Bt,
    const float* __restrict__ bias, const float* __restrict__ res,
    float* __restrict__ outf, __nv_bfloat16* __restrict__ outb,
    int N, int K, int flags)
{
    extern __shared__ __align__(16) char dsm[];

    const int tid  = threadIdx.x;
    const int wid  = tid >> 5;
    const int lane = tid & 31;
    const int warp_m = wid >> 2;   // 0..1 -> 32 rows each
    const int warp_n = wid & 3;    // 0..3 -> 32 cols each
    const int row0 = blockIdx.y * BM;
    const int col0 = blockIdx.x * BN;

    const uint32_t sbase = smem_u32(dsm);

    // load mapping: A 512 vec16 (2/thread), B 1024 vec16 (4/thread)
    const int a_row0 = tid >> 3;              // 0..31 (+32 for second)
    const int a_c8   = (tid & 7) << 3;        // 0..56

    float acc[2][4][4];
#pragma unroll
    for (int i = 0; i < 2; i++)
#pragma unroll
        for (int j = 0; j < 4; j++)
#pragma unroll
            for (int r = 0; r < 4; r++) acc[i][j][r] = 0.f;

    const int nch = K / BK;

    // prologue: issue chunks 0 and 1
#pragma unroll
    for (int p = 0; p < 2; p++) {
        int k0 = p * BK;
        uint32_t baseA = sbase + (uint32_t)(p * STAGE_BYTES);
        uint32_t baseB = baseA + A_BYTES;
#pragma unroll
        for (int v = 0; v < 2; v++) {
            int row = a_row0 + v * 32;
            CP_ASYNC16(baseA + (uint32_t)(row * PITCH + a_c8) * 2,
                       A + (size_t)(row0 + row) * K + k0 + a_c8);
        }
#pragma unroll
        for (int v = 0; v < 4; v++) {
            int row = a_row0 + v * 32;
            CP_ASYNC16(baseB + (uint32_t)(row * PITCH + a_c8) * 2,
                       Bt + (size_t)(col0 + row) * K + k0 + a_c8);
        }
        CP_COMMIT();
    }

    for (int ch = 0; ch < nch; ch++) {
        if (ch + 1 < nch) { CP_WAIT(1); } else { CP_WAIT(0); }
        __syncthreads();   // stage (ch+2)%STG last read at iter ch-1 -> safe to refill

        if (ch + 2 < nch) {
            int k0 = (ch + 2) * BK;
            int nb = (ch + 2) % STG;
            uint32_t baseA = sbase + (uint32_t)(nb * STAGE_BYTES);
            uint32_t baseB = baseA + A_BYTES;
#pragma unroll
            for (int v = 0; v < 2; v++) {
                int row = a_row0 + v * 32;
                CP_ASYNC16(baseA + (uint32_t)(row * PITCH + a_c8) * 2,
                           A + (size_t)(row0 + row) * K + k0 + a_c8);
            }
#pragma unroll
            for (int v = 0; v < 4; v++) {
                int row = a_row0 + v * 32;
                CP_ASYNC16(baseB + (uint32_t)(row * PITCH + a_c8) * 2,
                           Bt + (size_t)(col0 + row) * K + k0 + a_c8);
            }
            CP_COMMIT();
        }

        int buf = ch % STG;
        uint32_t aBase = sbase + (uint32_t)(buf * STAGE_BYTES);
        uint32_t bBase = aBase + A_BYTES;

#pragma unroll
        for (int kk = 0; kk < 4; kk++) {
            uint32_t a[2][4], b[4][2];
#pragma unroll
            for (int i = 0; i < 2; i++) {
                int r = warp_m * 32 + i * 16 + (lane & 15);
                int c = kk * 16 + ((lane >> 4) << 3);
                uint32_t addr = aBase + (uint32_t)(r * PITCH + c) * 2;
                asm volatile("ldmatrix.sync.aligned.m8n8.x4.shared.b16 {%0,%1,%2,%3}, [%4];"
                             : "=r"(a[i][0]), "=r"(a[i][1]), "=r"(a[i][2]), "=r"(a[i][3])
                             : "r"(addr));
            }
#pragma unroll
            for (int j = 0; j < 4; j++) {
                int r = warp_n * 32 + j * 8 + (lane & 7);
                int c = kk * 16 + (((lane >> 3) & 1) << 3);
                uint32_t addr = bBase + (uint32_t)(r * PITCH + c) * 2;
                asm volatile("ldmatrix.sync.aligned.m8n8.x2.shared.b16 {%0,%1}, [%2];"
                             : "=r"(b[j][0]), "=r"(b[j][1]) : "r"(addr));
            }
#pragma unroll
            for (int i = 0; i < 2; i++)
#pragma unroll
                for (int j = 0; j < 4; j++) {
                    asm volatile(
                        "mma.sync.aligned.m16n8k16.row.col.f32.bf16.bf16.f32 "
                        "{%0,%1,%2,%3}, {%4,%5,%6,%7}, {%8,%9}, {%0,%1,%2,%3};"
                        : "+f"(acc[i][j][0]), "+f"(acc[i][j][1]),
                          "+f"(acc[i][j][2]), "+f"(acc[i][j][3])
                        : "r"(a[i][0]), "r"(a[i][1]), "r"(a[i][2]), "r"(a[i][3]),
                          "r"(b[j][0]), "r"(b[j][1]));
                }
        }
    }

    // direct-fragment epilogue (round-8 proven)
    const int qr = lane >> 2;
    const int qc = (lane & 3) * 2;
#pragma unroll
    for (int i = 0; i < 2; i++) {
#pragma unroll
        for (int j = 0; j < 4; j++) {
            int gc = col0 + warp_n * 32 + j * 8 + qc;
#pragma unroll
            for (int half = 0; half < 2; half++) {
                int gr = row0 + warp_m * 32 + i * 16 + qr + half * 8;
                float v0 = acc[i][j][half * 2 + 0];
                float v1 = acc[i][j][half * 2 + 1];
                if (flags & GF_BIAS) { v0 += bias[gc]; v1 += bias[gc + 1]; }
                if (flags & GF_RES) {
                    const float* rp = res + (size_t)gr * N + gc;
                    v0 += rp[0]; v1 += rp[1];
                }
                if (flags & GF_RELU) { v0 = fmaxf(v0, 0.f); v1 = fmaxf(v1, 0.f); }
                if (outf) *(float2*)(outf + (size_t)gr * N + gc) = make_float2(v0, v1);
                if (outb) {
                    __nv_bfloat162 p = __floats2bfloat162_rn(v0, v1);
                    *(__nv_bfloat162*)(outb + (size_t)gr * N + gc) = p;
                }
            }
        }
    }
}

// ---------------- flash attention, double-buffered cp.async K/V ----------------
#define APITCH 24

__global__ __launch_bounds__(128) void fattn_kernel(
    const __nv_bfloat16* __restrict__ qkv, __nv_bfloat16* __restrict__ out)
{
    __shared__ __align__(16) __nv_bfloat16 Qs[64 * APITCH];
    __shared__ __align__(16) __nv_bfloat16 Ks[2][64 * APITCH];
    __shared__ __align__(16) __nv_bfloat16 Vs[2][64 * APITCH];

    const int qb = blockIdx.x;
    const int b  = blockIdx.y >> 4;
    const int h  = blockIdx.y & 15;
    const int tid = threadIdx.x, wm = tid >> 5, lane = tid & 31;
    const int g = lane >> 2, tig = lane & 3;
    const int LD = 3 * C_;
    const size_t base = (size_t)b * T_ * LD;

    const int l_row = tid >> 1, l_half = tid & 1;

    {
        const __nv_bfloat16* src = qkv + base + (size_t)(qb * 64 + l_row) * LD + h * D_ + l_half * 8;
        uint4 u = *(const uint4*)src;
        __nv_bfloat16 tmp[8]; *(uint4*)&tmp[0] = u;
#pragma unroll
        for (int i = 0; i < 8; i++)
            Qs[l_row * APITCH + l_half * 8 + i] =
                __float2bfloat16(__bfloat162float(tmp[i]) * QSCALE_);
        const uint4 ones_vec = make_uint4(0x00003F80u, 0u, 0u, 0u);
        *(uint4*)&Vs[l_half][l_row * APITCH + 16] = ones_vec;
    }

    {
        const __nv_bfloat16* ksrc = qkv + base + (size_t)l_row * LD + C_ + h * D_ + l_half * 8;
        CP_ASYNC16(smem_u32(&Ks[0][l_row * APITCH + l_half * 8]), ksrc);
        CP_ASYNC16(smem_u32(&Vs[0][l_row * APITCH + l_half * 8]), ksrc + C_);
        CP_COMMIT();
    }
    __syncthreads();

    uint32_t qa[4];
    {
        int r = wm * 16 + (lane & 15);
        int c = (lane >> 4) << 3;
        uint32_t addr = smem_u32(&Qs[r * APITCH + c]);
        asm volatile("ldmatrix.sync.aligned.m8n8.x4.shared.b16 {%0,%1,%2,%3}, [%4];"
                     : "=r"(qa[0]), "=r"(qa[1]), "=r"(qa[2]), "=r"(qa[3]) : "r"(addr));
    }

    float o[3][4];
#pragma unroll
    for (int n = 0; n < 3; n++)
#pragma unroll
        for (int r = 0; r < 4; r++) o[n][r] = 0.f;

    for (int kt = 0; kt <= qb; kt++) {
        CP_WAIT(0);
        __syncthreads();

        if (kt < qb) {
            const __nv_bfloat16* ksrc = qkv + base + (size_t)((kt + 1) * 64 + l_row) * LD + C_ + h * D_ + l_half * 8;
            int nb = (kt + 1) & 1;
            CP_ASYNC16(smem_u32(&Ks[nb][l_row * APITCH + l_half * 8]), ksrc);
            CP_ASYNC16(smem_u32(&Vs[nb][l_row * APITCH + l_half * 8]), ksrc + C_);
            CP_COMMIT();
        }

        const __nv_bfloat16* Kb = Ks[kt & 1];
        const __nv_bfloat16* Vb = Vs[kt & 1];

        float s[8][4];
#pragma unroll
        for (int f = 0; f < 8; f++) {
            uint32_t b0, b1;
            int r = f * 8 + (lane & 7);
            int c = ((lane >> 3) & 1) << 3;
            uint32_t addr = smem_u32(&Kb[r * APITCH + c]);
            asm volatile("ldmatrix.sync.aligned.m8n8.x2.shared.b16 {%0,%1}, [%2];"
                         : "=r"(b0), "=r"(b1) : "r"(addr));
            s[f][0] = s[f][1] = s[f][2] = s[f][3] = 0.f;
            asm volatile(
                "mma.sync.aligned.m16n8k16.row.col.f32.bf16.bf16.f32 "
                "{%0,%1,%2,%3}, {%4,%5,%6,%7}, {%8,%9}, {%0,%1,%2,%3};"
                : "+f"(s[f][0]), "+f"(s[f][1]), "+f"(s[f][2]), "+f"(s[f][3])
                : "r"(qa[0]), "r"(qa[1]), "r"(qa[2]), "r"(qa[3]), "r"(b0), "r"(b1));
        }

        if (kt == qb) {
            int q0 = wm * 16 + g, q1 = q0 + 8;
#pragma unroll
            for (int f = 0; f < 8; f++) {
                int k0 = f * 8 + 2 * tig;
                if (k0     > q0) s[f][0] = -1e30f;
                if (k0 + 1 > q0) s[f][1] = -1e30f;
                if (k0     > q1) s[f][2] = -1e30f;
                if (k0 + 1 > q1) s[f][3] = -1e30f;
            }
        }

        uint32_t pa[8][2];
#pragma unroll
        for (int f = 0; f < 8; f++) {
            float p0 = ex2f(s[f][0]), p1 = ex2f(s[f][1]);
            float p2 = ex2f(s[f][2]), p3 = ex2f(s[f][3]);
            __nv_bfloat162 u = __floats2bfloat162_rn(p0, p1);
            __nv_bfloat162 w = __floats2bfloat162_rn(p2, p3);
            pa[f][0] = *(uint32_t*)&u;
            pa[f][1] = *(uint32_t*)&w;
        }

#pragma unroll
        for (int j2 = 0; j2 < 4; j2++) {
            int vr = j2 * 16 + (lane & 15);
#pragma unroll
            for (int n = 0; n < 3; n++) {
                uint32_t b0, b1;
                uint32_t addr = smem_u32(&Vb[vr * APITCH + n * 8]);
                asm volatile("ldmatrix.sync.aligned.m8n8.x2.trans.shared.b16 {%0,%1}, [%2];"
                             : "=r"(b0), "=r"(b1) : "r"(addr));
                asm volatile(
                    "mma.sync.aligned.m16n8k16.row.col.f32.bf16.bf16.f32 "
                    "{%0,%1,%2,%3}, {%4,%5,%6,%7}, {%8,%9}, {%0,%1,%2,%3};"
                    : "+f"(o[n][0]), "+f"(o[n][1]), "+f"(o[n][2]), "+f"(o[n][3])
                    : "r"(pa[2*j2][0]), "r"(pa[2*j2][1]),
                      "r"(pa[2*j2+1][0]), "r"(pa[2*j2+1][1]),
                      "r"(b0), "r"(b1));
            }
        }
    }

    float l0 = __shfl_sync(0xffffffffu, o[2][0], lane & ~3);
    float l1 = __shfl_sync(0xffffffffu, o[2][2], lane & ~3);
    float inv0 = 1.f / l0, inv1 = 1.f / l1;

    int gr0 = qb * 64 + wm * 16 + g;
    int gr1 = gr0 + 8;
#pragma unroll
    for (int n = 0; n < 2; n++) {
        int gc = h * D_ + n * 8 + 2 * tig;
        __nv_bfloat162 p0 = __floats2bfloat162_rn(o[n][0] * inv0, o[n][1] * inv0);
        __nv_bfloat162 p1 = __floats2bfloat162_rn(o[n][2] * inv1, o[n][3] * inv1);
        *(__nv_bfloat162*)(out + (size_t)(b * T_ + gr0) * C_ + gc) = p0;
        *(__nv_bfloat162*)(out + (size_t)(b * T_ + gr1) * C_ + gc) = p1;
    }
}

// ---------------- host ----------------
extern "C" void kernel_launch(void* const* d_in, const int* in_sizes, int n_in,
                              void* d_out, int out_size)
{
    const float* x   = (const float*)d_in[0];
    const float* Wq  = (const float*)d_in[1];
    const float* Wk  = (const float*)d_in[2];
    const float* Wv  = (const float*)d_in[3];
    const float* Wp  = (const float*)d_in[4];
    const float* bp  = (const float*)d_in[5];
    const float* W1  = (const float*)d_in[6];
    const float* b1  = (const float*)d_in[7];
    const float* W2  = (const float*)d_in[8];
    const float* b2  = (const float*)d_in[9];
    const float* g1  = (const float*)d_in[10];
    const float* be1 = (const float*)d_in[11];
    const float* g2  = (const float*)d_in[12];
    const float* be2 = (const float*)d_in[13];
    float* out = (float*)d_out;

    __nv_bfloat16 *h1b, *attb, *h2b, *h3b, *qkvb, *wqkvt, *wpt, *w1t, *w2t;
    float *x2;
    cudaGetSymbolAddress((void**)&h1b,   g_h1b);
    cudaGetSymbolAddress((void**)&attb,  g_attb);
    cudaGetSymbolAddress((void**)&h2b,   g_h2b);
    cudaGetSymbolAddress((void**)&h3b,   g_h3b);
    cudaGetSymbolAddress((void**)&qkvb,  g_qkvb);
    cudaGetSymbolAddress((void**)&x2,    g_x2);
    cudaGetSymbolAddress((void**)&wqkvt, g_wqkvt);
    cudaGetSymbolAddress((void**)&wpt,   g_wpt);
    cudaGetSymbolAddress((void**)&w1t,   g_w1t);
    cudaGetSymbolAddress((void**)&w2t,   g_w2t);

    cudaFuncSetAttribute(mma_gemm, cudaFuncAttributeMaxDynamicSharedMemorySize, GEMM_DSM);

    // prep: weight transposes + ln1 in one launch
    prep_kernel<<<768 + M_/8, 256>>>(Wq, Wk, Wv, Wp, W1, W2,
                                     wqkvt, wpt, w1t, w2t,
                                     x, g1, be1, h1b);

    // qkv = h1 @ [Wq|Wk|Wv] (bf16 out)
    mma_gemm<<<dim3(6, M_/BM), 256, GEMM_DSM>>>(h1b, wqkvt, nullptr, nullptr,
                                                nullptr, qkvb, 3*C_, C_, 0);
    // flash attention -> attb bf16
    fattn_kernel<<<dim3(T_/64, B_*H_), 128>>>(qkvb, attb);

    // x2 = x + attb @ Wp^T + bp
    mma_gemm<<<dim3(2, M_/BM), 256, GEMM_DSM>>>(attb, wpt, bp, x,
                                                x2, nullptr, C_, C_, GF_BIAS | GF_RES);
    // ln2 -> h2 bf16
    ln_kernel<<<M_/8, 256>>>(x2, g2, be2, h2b);

    // h3 = relu(h2 @ W1^T + b1)
    mma_gemm<<<dim3(8, M_/BM), 256, GEMM_DSM>>>(h2b, w1t, b1, nullptr,
                                                nullptr, h3b, FF_, C_, GF_BIAS | GF_RELU);
    // out = x2 + h3 @ W2^T + b2
    mma_gemm<<<dim3(2, M_/BM), 256, GEMM_DSM>>>(h3b, w2t, b2, x2,
                                                out, nullptr, C_, FF_, GF_BIAS | GF_RES);
}